// round 11
// baseline (speedup 1.0000x reference)
#include <cuda_runtime.h>

#define NN 512
#define PP 130816
typedef unsigned long long ull;

__device__ float g_ca[NN*512];
__device__ float g_cb[NN*512];
__device__ float g_sa[NN*256];
__device__ float g_sb[NN*256];

__device__ __forceinline__ ull pack2(float lo, float hi) {
    ull r; asm("mov.b64 %0, {%1, %2};" : "=l"(r) : "f"(lo), "f"(hi)); return r;
}
__device__ __forceinline__ void fma2(ull& d, ull a, ull b) {
    asm("fma.rn.f32x2 %0, %1, %2, %0;" : "+l"(d) : "l"(a), "l"(b));
}
__device__ __forceinline__ ull add2(ull a, ull b) {
    ull r; asm("add.rn.f32x2 %0, %1, %2;" : "=l"(r) : "l"(a), "l"(b)); return r;
}
__device__ __forceinline__ float2 unpack2(ull v) {
    float2 f; asm("mov.b64 {%0, %1}, %2;" : "=f"(f.x), "=f"(f.y) : "l"(v)); return f;
}

// ---------------------------------------------------------------------------
// Phase 1: C = F(512x512) @ B(512 x 1536 concat). BM=64, BN=64, BK=32,
// 256 threads, grid (24,8) = 192 blocks, double-buffered dynamic smem.
// Per-thread 4Mx4N via f32x2 M-pairs; B staged duplicated (b,b).
// smem: As float[2][32*68] | Bs ull[2][32*64]
// ---------------------------------------------------------------------------
__global__ __launch_bounds__(256) void proj_gemm(const float* __restrict__ F,
                                                 const float* __restrict__ cw1,
                                                 const float* __restrict__ sw1) {
    extern __shared__ float smraw[];
    float* As = smraw;                        // 2 x 2176 floats
    ull*   Bs = (ull*)(smraw + 4352);         // 2 x 2048 ulls
    int t = threadIdx.x;
    int cglob = blockIdx.x * 64;
    const float* Bp; float* Cp; int ldb, bcol;
    if (cglob < 512)       { Bp = cw1;             Cp = g_ca; ldb = 512; bcol = cglob; }
    else if (cglob < 1024) { Bp = cw1 + 512 * 512; Cp = g_cb; ldb = 512; bcol = cglob - 512; }
    else if (cglob < 1280) { Bp = sw1;             Cp = g_sa; ldb = 256; bcol = cglob - 1024; }
    else                   { Bp = sw1 + 512 * 256; Cp = g_sb; ldb = 256; bcol = cglob - 1280; }
    int rb = blockIdx.y * 64;
    int rowg = t & 15, colg = t >> 4;

    ull acc[2][4];
#pragma unroll
    for (int a = 0; a < 2; a++)
#pragma unroll
        for (int b = 0; b < 4; b++) acc[a][b] = 0ull;

    float4 pa[2], pb[2];
#pragma unroll
    for (int it = 0; it < 2; it++) {
        int idx = t + it * 256, row = idx >> 3, q8 = idx & 7;
        pa[it] = *(const float4*)&F[(rb + row) * 512 + q8 * 4];
    }
#pragma unroll
    for (int it = 0; it < 2; it++) {
        int idx = t + it * 256, k = idx >> 4, q16 = idx & 15;
        pb[it] = *(const float4*)&Bp[k * ldb + bcol + q16 * 4];
    }
#pragma unroll
    for (int it = 0; it < 2; it++) {
        int idx = t + it * 256, row = idx >> 3, q8 = idx & 7;
        As[(q8 * 4 + 0) * 68 + row] = pa[it].x;
        As[(q8 * 4 + 1) * 68 + row] = pa[it].y;
        As[(q8 * 4 + 2) * 68 + row] = pa[it].z;
        As[(q8 * 4 + 3) * 68 + row] = pa[it].w;
    }
#pragma unroll
    for (int it = 0; it < 2; it++) {
        int idx = t + it * 256, k = idx >> 4, q16 = idx & 15;
        Bs[k * 64 + q16 * 4 + 0] = pack2(pb[it].x, pb[it].x);
        Bs[k * 64 + q16 * 4 + 1] = pack2(pb[it].y, pb[it].y);
        Bs[k * 64 + q16 * 4 + 2] = pack2(pb[it].z, pb[it].z);
        Bs[k * 64 + q16 * 4 + 3] = pack2(pb[it].w, pb[it].w);
    }
    __syncthreads();

    for (int tile = 0; tile < 16; tile++) {
        int cur = tile & 1;
        if (tile < 15) {
            int k0 = (tile + 1) * 32;
#pragma unroll
            for (int it = 0; it < 2; it++) {
                int idx = t + it * 256, row = idx >> 3, q8 = idx & 7;
                pa[it] = *(const float4*)&F[(rb + row) * 512 + k0 + q8 * 4];
            }
#pragma unroll
            for (int it = 0; it < 2; it++) {
                int idx = t + it * 256, k = idx >> 4, q16 = idx & 15;
                pb[it] = *(const float4*)&Bp[(k0 + k) * ldb + bcol + q16 * 4];
            }
        }
        const float* Ac = As + cur * 2176;
        const ull*   Bc = Bs + cur * 2048;
#pragma unroll
        for (int k = 0; k < 32; k++) {
            ulonglong2 aA = *(const ulonglong2*)&Ac[k * 68 + rowg * 4];
            ulonglong2 b0 = *(const ulonglong2*)&Bc[k * 64 + colg * 4];
            ulonglong2 b1 = *(const ulonglong2*)&Bc[k * 64 + colg * 4 + 2];
            fma2(acc[0][0], aA.x, b0.x); fma2(acc[0][1], aA.x, b0.y);
            fma2(acc[0][2], aA.x, b1.x); fma2(acc[0][3], aA.x, b1.y);
            fma2(acc[1][0], aA.y, b0.x); fma2(acc[1][1], aA.y, b0.y);
            fma2(acc[1][2], aA.y, b1.x); fma2(acc[1][3], aA.y, b1.y);
        }
        if (tile < 15) {
            int nxt = cur ^ 1;
#pragma unroll
            for (int it = 0; it < 2; it++) {
                int idx = t + it * 256, row = idx >> 3, q8 = idx & 7;
                As[nxt * 2176 + (q8 * 4 + 0) * 68 + row] = pa[it].x;
                As[nxt * 2176 + (q8 * 4 + 1) * 68 + row] = pa[it].y;
                As[nxt * 2176 + (q8 * 4 + 2) * 68 + row] = pa[it].z;
                As[nxt * 2176 + (q8 * 4 + 3) * 68 + row] = pa[it].w;
            }
#pragma unroll
            for (int it = 0; it < 2; it++) {
                int idx = t + it * 256, k = idx >> 4, q16 = idx & 15;
                Bs[nxt * 2048 + k * 64 + q16 * 4 + 0] = pack2(pb[it].x, pb[it].x);
                Bs[nxt * 2048 + k * 64 + q16 * 4 + 1] = pack2(pb[it].y, pb[it].y);
                Bs[nxt * 2048 + k * 64 + q16 * 4 + 2] = pack2(pb[it].z, pb[it].z);
                Bs[nxt * 2048 + k * 64 + q16 * 4 + 3] = pack2(pb[it].w, pb[it].w);
            }
        }
        __syncthreads();
    }
#pragma unroll
    for (int mp = 0; mp < 2; mp++) {
        int r = rb + rowg * 4 + mp * 2;
#pragma unroll
        for (int n = 0; n < 4; n++) {
            float2 f = unpack2(acc[mp][n]);
            int c = bcol + colg * 4 + n;
            Cp[r * ldb + c] = f.x;
            Cp[(r + 1) * ldb + c] = f.y;
        }
    }
}

// ---------------------------------------------------------------------------
// Phase 2: 512 threads = 16 warps, tile 32j x 32i, 2 pairs/lane
// (warp w -> i = 2w, 2w+1; lane -> j). K-PAIRED h packing:
// h = add2(a_kpair, b_kpair) -> zero pack MOVs; cw2 staged as
// wp[kp][c] = (w[2kp][c], w[2kp+1][c]). Accumulators hold k-parity partials.
// smem floats: bC 32x516 (cb1 folded) | aC 32x512 | wp 2560 ull.
// Strength overlays same regions after a resync.
// ---------------------------------------------------------------------------
#define O_BC 0
#define O_AC 16512
#define O_WP 32896
#define SMEMF 38016

__global__ __launch_bounds__(512) void pair_kernel(
    const float* __restrict__ cb1, const float* __restrict__ cw2,
    const float* __restrict__ cb2, const float* __restrict__ sb1,
    const float* __restrict__ sw2, const float* __restrict__ sb2,
    float* __restrict__ out)
{
    extern __shared__ float sm[];
    int bid = blockIdx.x;
    int jb = (int)((sqrtf(8.0f * bid + 1.0f) - 1.0f) * 0.5f);
    while ((jb + 1) * (jb + 2) / 2 <= bid) jb++;
    while (jb * (jb + 1) / 2 > bid) jb--;
    int ib = bid - jb * (jb + 1) / 2;
    int jbase = jb * 32, ibase = ib * 32;
    int t = threadIdx.x;
    int w = t >> 5, lane = t & 31;

    // stage bC (32x516, cb1 folded)
#pragma unroll
    for (int it = 0; it < 8; it++) {
        int idx = t + it * 512;
        int r = idx >> 7, q = (idx & 127) * 4;
        float4 vb = *(const float4*)&g_cb[(jbase + r) * 512 + q];
        float4 vc = *(const float4*)&cb1[q];
        vb.x += vc.x; vb.y += vc.y; vb.z += vc.z; vb.w += vc.w;
        *(float4*)&sm[O_BC + r * 516 + q] = vb;
    }
    // stage aC (32x512, plain rows)
#pragma unroll
    for (int it = 0; it < 8; it++) {
        int idx = t + it * 512;
        int r = idx >> 7, q = (idx & 127) * 4;
        *(float4*)&sm[O_AC + r * 512 + q] = *(const float4*)&g_ca[(ibase + r) * 512 + q];
    }
    // stage wp: kp-paired cw2
    {
        ull* wp = (ull*)&sm[O_WP];
        for (int idx = t; idx < 2560; idx += 512) {
            int kp = idx / 10, c = idx - kp * 10;
            wp[idx] = pack2(cw2[kp * 20 + c], cw2[kp * 20 + 10 + c]);
        }
    }
    __syncthreads();

    const float* bRow  = &sm[O_BC + lane * 516];
    const float* aRow0 = &sm[O_AC + (2 * w) * 512];
    const float* aRow1 = aRow0 + 512;
    const ull*   wp    = (const ull*)&sm[O_WP];

    ull acc0[10], acc1[10];
#pragma unroll
    for (int c = 0; c < 10; c++) { acc0[c] = 0ull; acc1[c] = 0ull; }

    for (int k0 = 0; k0 < 512; k0 += 4) {
        ulonglong2 bp = *(const ulonglong2*)(bRow + k0);
        ulonglong2 a0 = *(const ulonglong2*)(aRow0 + k0);
        ulonglong2 a1 = *(const ulonglong2*)(aRow1 + k0);
        ull s00 = add2(a0.x, bp.x), s01 = add2(a0.y, bp.y);
        ull s10 = add2(a1.x, bp.x), s11 = add2(a1.y, bp.y);
        float2 f00 = unpack2(s00), f01 = unpack2(s01);
        float2 f10 = unpack2(s10), f11 = unpack2(s11);
        ull h00 = pack2(fmaxf(f00.x, 0.f), fmaxf(f00.y, 0.f));
        ull h01 = pack2(fmaxf(f01.x, 0.f), fmaxf(f01.y, 0.f));
        ull h10 = pack2(fmaxf(f10.x, 0.f), fmaxf(f10.y, 0.f));
        ull h11 = pack2(fmaxf(f11.x, 0.f), fmaxf(f11.y, 0.f));
        const ulonglong2* wA = (const ulonglong2*)(wp + (k0 >> 1) * 10);
        const ulonglong2* wB = (const ulonglong2*)(wp + (k0 >> 1) * 10 + 10);
#pragma unroll
        for (int q = 0; q < 5; q++) {
            ulonglong2 wa = wA[q];
            fma2(acc0[2 * q],     h00, wa.x); fma2(acc0[2 * q + 1], h00, wa.y);
            fma2(acc1[2 * q],     h10, wa.x); fma2(acc1[2 * q + 1], h10, wa.y);
            ulonglong2 wb = wB[q];
            fma2(acc0[2 * q],     h01, wb.x); fma2(acc0[2 * q + 1], h01, wb.y);
            fma2(acc1[2 * q],     h11, wb.x); fma2(acc1[2 * q + 1], h11, wb.y);
        }
    }

    // ---- strength path: overlay same smem ----
    __syncthreads();
#pragma unroll
    for (int it = 0; it < 4; it++) {   // bS 32x260 (+sb1)
        int idx = t + it * 512;
        int r = idx >> 6, q = (idx & 63) * 4;
        float4 vb = *(const float4*)&g_sb[(jbase + r) * 256 + q];
        float4 vc = *(const float4*)&sb1[q];
        vb.x += vc.x; vb.y += vc.y; vb.z += vc.z; vb.w += vc.w;
        *(float4*)&sm[O_BC + r * 260 + q] = vb;
    }
#pragma unroll
    for (int it = 0; it < 4; it++) {   // aS 32x256 plain
        int idx = t + it * 512;
        int r = idx >> 6, q = (idx & 63) * 4;
        *(float4*)&sm[O_AC + r * 256 + q] = *(const float4*)&g_sa[(ibase + r) * 256 + q];
    }
    if (t < 128) ((ull*)&sm[O_WP])[t] = pack2(sw2[2 * t], sw2[2 * t + 1]);
    __syncthreads();

    ull sa0 = 0ull, sa1 = 0ull;
    {
        const float* sbRow  = &sm[O_BC + lane * 260];
        const float* sRow0  = &sm[O_AC + (2 * w) * 256];
        const float* sRow1  = sRow0 + 256;
        const ull*   swp    = (const ull*)&sm[O_WP];
        for (int k0 = 0; k0 < 256; k0 += 4) {
            ulonglong2 bp = *(const ulonglong2*)(sbRow + k0);
            ulonglong2 a0 = *(const ulonglong2*)(sRow0 + k0);
            ulonglong2 a1 = *(const ulonglong2*)(sRow1 + k0);
            ulonglong2 ww = *(const ulonglong2*)(swp + (k0 >> 1));
            ull s00 = add2(a0.x, bp.x), s01 = add2(a0.y, bp.y);
            ull s10 = add2(a1.x, bp.x), s11 = add2(a1.y, bp.y);
            float2 f00 = unpack2(s00), f01 = unpack2(s01);
            float2 f10 = unpack2(s10), f11 = unpack2(s11);
            fma2(sa0, pack2(fmaxf(f00.x, 0.f), fmaxf(f00.y, 0.f)), ww.x);
            fma2(sa0, pack2(fmaxf(f01.x, 0.f), fmaxf(f01.y, 0.f)), ww.y);
            fma2(sa1, pack2(fmaxf(f10.x, 0.f), fmaxf(f10.y, 0.f)), ww.x);
            fma2(sa1, pack2(fmaxf(f11.x, 0.f), fmaxf(f11.y, 0.f)), ww.y);
        }
    }

    // ---- epilogue (2 pairs per lane) ----
    int j = jbase + lane;
    float b2[10];
#pragma unroll
    for (int c = 0; c < 10; c++) b2[c] = __ldg(&cb2[c]);
    float sbv = __ldg(&sb2[0]);
#pragma unroll
    for (int s = 0; s < 2; s++) {
        int i = ibase + 2 * w + s;
        if (j <= i) continue;
        float l[10];
#pragma unroll
        for (int c = 0; c < 10; c++) {
            float2 f = unpack2(s ? acc1[c] : acc0[c]);
            l[c] = f.x + f.y + b2[c];
        }
        float m = l[0]; int idx = 0;
#pragma unroll
        for (int c = 1; c < 10; c++) if (l[c] > m) { m = l[c]; idx = c; }
        float sum = 0.f;
#pragma unroll
        for (int c = 0; c < 10; c++) sum += __expf(l[c] - m);
        float lse = m + __logf(sum);
        int p = i * (1023 - i) / 2 + j - i - 1;
        float2* o2 = (float2*)(out + (size_t)p * 10);
#pragma unroll
        for (int q = 0; q < 5; q++)
            o2[q] = make_float2(l[2 * q] - lse, l[2 * q + 1] - lse);
        out[10 * PP + p] = (float)idx;
        float2 fs = unpack2(s ? sa1 : sa0);
        float x = fs.x + fs.y + sbv;
        out[11 * PP + p] = 1.f / (1.f + __expf(-x));
    }
}

extern "C" void kernel_launch(void* const* d_in, const int* in_sizes, int n_in,
                              void* d_out, int out_size) {
    (void)in_sizes; (void)n_in; (void)out_size;
    const float* features = (const float*)d_in[0];
    const float* cw1 = (const float*)d_in[1];
    const float* cb1 = (const float*)d_in[2];
    const float* cw2 = (const float*)d_in[3];
    const float* cb2 = (const float*)d_in[4];
    const float* sw1 = (const float*)d_in[5];
    const float* sb1 = (const float*)d_in[6];
    const float* sw2 = (const float*)d_in[7];
    const float* sb2 = (const float*)d_in[8];
    float* out = (float*)d_out;

    cudaFuncSetAttribute(proj_gemm, cudaFuncAttributeMaxDynamicSharedMemorySize, 50176);
    cudaFuncSetAttribute(pair_kernel, cudaFuncAttributeMaxDynamicSharedMemorySize,
                         SMEMF * sizeof(float));

    proj_gemm<<<dim3(24, 8), 256, 50176>>>(features, cw1, sw1);
    pair_kernel<<<136, 512, SMEMF * sizeof(float)>>>(
        cb1, cw2, cb2, sb1, sw2, sb2, out);
}